// round 11
// baseline (speedup 1.0000x reference)
#include <cuda_runtime.h>
#include <cuda_bf16.h>

// QueryAndGroup, four-kernel version.
//   t1: xyz (B,N,3) -> SoA xs/ys/zs + precomputed p2 (exact recipe)
//   t2: feat (B,C,N) -> feat_T (B,N,C)        (for coalesced gathers)
//   k1: ball query, 128 points/warp-iter, precomputed p2, bit-exact d2
//   k2: block-per-query grouping: coalesced 256B gathers via feat_T, smem
//       transpose, coalesced float4 channel-major stores.
// Shapes: B=4, N=16384, S=4096, C=64, K=64, radius=0.2. Out: (B, 67, S, K) f32.

namespace {
constexpr int B = 4;
constexpr int N = 16384;
constexpr int S = 4096;
constexpr int C = 64;
constexpr int K = 64;
constexpr float R2 = 0.04f;
constexpr int WARPS_PER_BLOCK = 4;     // smaller blocks: less max-of-warps imbalance
constexpr int THREADS = WARPS_PER_BLOCK * 32;
}

// Static scratch (no allocations allowed).
__device__ __align__(256) float g_featT[(size_t)B * N * C];   // 16.8 MB
__device__ __align__(16)  float g_xs[B * N];
__device__ __align__(16)  float g_ys[B * N];
__device__ __align__(16)  float g_zs[B * N];
__device__ __align__(16)  float g_p2[B * N];                  // precomputed |p|^2
__device__ int g_idx[B * S * K];                              // 4 MB

// p2/q2 recipe (verified rel_err == 0.0 in R7): (x^2 + z^2) + y^2, rounded muls.
__device__ __forceinline__ float sq_norm_exact(float x, float y, float z)
{
    return __fadd_rn(__fadd_rn(__fmul_rn(x, x), __fmul_rn(z, z)),
                     __fmul_rn(y, y));
}

// d2 combine with precomputed p2 (qpd ascending FMA chain; verified recipe).
__device__ __forceinline__ float d2_pre(float qx, float qy, float qz, float q2,
                                        float px, float py, float pz, float p2)
{
    const float qpd = __fmaf_rn(qz, pz, __fmaf_rn(qy, py, __fmul_rn(qx, px)));
    return __fsub_rn(__fadd_rn(q2, p2), __fmul_rn(2.0f, qpd));
}

// ---------------------------------------------------------------------------
// t1: xyz (B,N,3) -> SoA + p2
// ---------------------------------------------------------------------------
__global__ void transpose_xyz_kernel(const float* __restrict__ xyz)
{
    const int i = blockIdx.x * blockDim.x + threadIdx.x;   // b*N + n
    if (i >= B * N) return;
    const float* p = xyz + (size_t)i * 3;
    const float x = p[0], y = p[1], z = p[2];
    g_xs[i] = x;
    g_ys[i] = y;
    g_zs[i] = z;
    g_p2[i] = sq_norm_exact(x, y, z);
}

// ---------------------------------------------------------------------------
// t2: feat (B,C,N) -> feat_T (B,N,C), tiled smem transpose
// ---------------------------------------------------------------------------
__global__ void transpose_feat_kernel(const float* __restrict__ feat)
{
    __shared__ float tile[32][33];
    const int b  = blockIdx.z;
    const int n0 = blockIdx.x * 32;
    const int c0 = blockIdx.y * 32;
    const int tx = threadIdx.x;      // 0..31
    const int ty = threadIdx.y;      // 0..7

    const float* fb = feat + (size_t)b * C * N;
#pragma unroll
    for (int i = 0; i < 32; i += 8)
        tile[ty + i][tx] = fb[(size_t)(c0 + ty + i) * N + n0 + tx];
    __syncthreads();

    float* fo = g_featT + (size_t)b * N * C;
#pragma unroll
    for (int i = 0; i < 32; i += 8)
        fo[(size_t)(n0 + ty + i) * C + c0 + tx] = tile[tx][ty + i];
}

// ---------------------------------------------------------------------------
// k1: ball query. Warp per query, 128 points per iteration (4/lane, lane-major
// so global ascending order = (lane, j) lexicographic). Exact first-K via
// 4 ballots + prefix popc. d2 math identical to the verified recipe, with p2
// streamed from the precomputed array.
// ---------------------------------------------------------------------------
__global__ __launch_bounds__(THREADS)
void ball_query_kernel(const float* __restrict__ xyz,      // (B, N, 3)
                       const float* __restrict__ new_xyz,  // (B, S, 3)
                       float* __restrict__ out)            // (B, 3+C, S, K)
{
    __shared__ int s_idx[WARPS_PER_BLOCK][K];

    const int warp = threadIdx.x >> 5;
    const int lane = threadIdx.x & 31;
    const int q = blockIdx.x * WARPS_PER_BLOCK + warp;
    if (q >= B * S) return;
    const int b = q / S;
    const int s = q - b * S;

    const float* qp_ptr = new_xyz + ((size_t)b * S + s) * 3;
    const float qx = qp_ptr[0], qy = qp_ptr[1], qz = qp_ptr[2];
    const float q2 = sq_norm_exact(qx, qy, qz);

    const float4* xs4 = (const float4*)(g_xs + b * N);
    const float4* ys4 = (const float4*)(g_ys + b * N);
    const float4* zs4 = (const float4*)(g_zs + b * N);
    const float4* p24 = (const float4*)(g_p2 + b * N);

    int count = 0;
    for (int base = 0; base < N; base += 128) {
        const int v = (base >> 2) + lane;
        const float4 X = xs4[v];
        const float4 Y = ys4[v];
        const float4 Z = zs4[v];
        const float4 P = p24[v];

        const bool h0 = d2_pre(qx, qy, qz, q2, X.x, Y.x, Z.x, P.x) < R2;
        const bool h1 = d2_pre(qx, qy, qz, q2, X.y, Y.y, Z.y, P.y) < R2;
        const bool h2 = d2_pre(qx, qy, qz, q2, X.z, Y.z, Z.z, P.z) < R2;
        const bool h3 = d2_pre(qx, qy, qz, q2, X.w, Y.w, Z.w, P.w) < R2;

        const unsigned m0 = __ballot_sync(0xffffffffu, h0);
        const unsigned m1 = __ballot_sync(0xffffffffu, h1);
        const unsigned m2 = __ballot_sync(0xffffffffu, h2);
        const unsigned m3 = __ballot_sync(0xffffffffu, h3);

        const unsigned below = (1u << lane) - 1u;
        int p = count + __popc(m0 & below) + __popc(m1 & below)
                      + __popc(m2 & below) + __popc(m3 & below);
        const int n0 = base + 4 * lane;
        if (h0 && p < K) s_idx[warp][p] = n0;
        p += h0;
        if (h1 && p < K) s_idx[warp][p] = n0 + 1;
        p += h1;
        if (h2 && p < K) s_idx[warp][p] = n0 + 2;
        p += h2;
        if (h3 && p < K) s_idx[warp][p] = n0 + 3;

        count += __popc(m0) + __popc(m1) + __popc(m2) + __popc(m3);
        if (count >= K) break;
    }
    __syncwarp();

    const int k0 = 2 * lane;
    const int cnt = (count < K) ? count : K;
    const int fill = (cnt > 0) ? s_idx[warp][0] : 0;
    if (k0 >= cnt)     s_idx[warp][k0]     = fill;
    if (k0 + 1 >= cnt) s_idx[warp][k0 + 1] = fill;
    __syncwarp();

    const int i0 = s_idx[warp][k0];
    const int i1 = s_idx[warp][k0 + 1];

    *reinterpret_cast<int2*>(g_idx + (size_t)q * K + k0) = make_int2(i0, i1);

    // grouped_xyz = xyz[idx] - new_xyz (channels 0..2)
    const float* xb = xyz + (size_t)b * N * 3;
    const size_t chan_stride = (size_t)S * K;
    float* ob = out + (size_t)b * (3 + C) * chan_stride + (size_t)s * K + k0;
    {
        const float x0 = xb[3 * i0 + 0], y0 = xb[3 * i0 + 1], z0 = xb[3 * i0 + 2];
        const float x1 = xb[3 * i1 + 0], y1 = xb[3 * i1 + 1], z1 = xb[3 * i1 + 2];
        *reinterpret_cast<float2*>(ob + 0 * chan_stride) =
            make_float2(__fsub_rn(x0, qx), __fsub_rn(x1, qx));
        *reinterpret_cast<float2*>(ob + 1 * chan_stride) =
            make_float2(__fsub_rn(y0, qy), __fsub_rn(y1, qy));
        *reinterpret_cast<float2*>(ob + 2 * chan_stride) =
            make_float2(__fsub_rn(z0, qz), __fsub_rn(z1, qz));
    }
}

// ---------------------------------------------------------------------------
// k2: grouping. Block = one query (128 threads). Gather 64 indices x 256B
// (coalesced: 16 lanes per index, LDG.128), stage transposed in smem
// [k][c] with +1 padding, then write channel-major float4 coalesced.
// ---------------------------------------------------------------------------
__global__ __launch_bounds__(128)
void group_feat_kernel(float* __restrict__ out)
{
    __shared__ int   sidx[K];
    __shared__ float sdata[K][C + 1];   // 64 x 65 floats, pad limits conflicts

    const int q = blockIdx.x;
    const int b = q / S;
    const int s = q - b * S;
    const int t = threadIdx.x;

    if (t < 16)
        *reinterpret_cast<int4*>(sidx + t * 4) =
            *reinterpret_cast<const int4*>(g_idx + (size_t)q * K + t * 4);
    __syncthreads();

    const float* ft = g_featT + (size_t)b * N * C;

    // Gather phase: 1024 float4 slots (64 idx x 16 parts), 8 per thread.
#pragma unroll
    for (int jj = 0; jj < 8; ++jj) {
        const int slot = jj * 128 + t;
        const int k    = slot >> 4;
        const int part = slot & 15;
        const int idx  = sidx[k];
        const float4 v = *reinterpret_cast<const float4*>(ft + (size_t)idx * C + part * 4);
        float* d = &sdata[k][part * 4];
        d[0] = v.x; d[1] = v.y; d[2] = v.z; d[3] = v.w;
    }
    __syncthreads();

    // Write phase: out[b][3+c][s][k], 1024 float4 slots (64 c x 16 k-parts).
    float* ob = out + ((size_t)b * (3 + C) + 3) * ((size_t)S * K) + (size_t)s * K;
#pragma unroll
    for (int jj = 0; jj < 8; ++jj) {
        const int slot = jj * 128 + t;
        const int c    = slot >> 4;
        const int kp   = (slot & 15) * 4;
        const float4 v = make_float4(sdata[kp + 0][c], sdata[kp + 1][c],
                                     sdata[kp + 2][c], sdata[kp + 3][c]);
        *reinterpret_cast<float4*>(ob + (size_t)c * (S * K) + kp) = v;
    }
}

extern "C" void kernel_launch(void* const* d_in, const int* in_sizes, int n_in,
                              void* d_out, int out_size)
{
    const float* xyz     = (const float*)d_in[0];  // B*N*3
    const float* new_xyz = (const float*)d_in[1];  // B*S*3
    const float* feat    = (const float*)d_in[2];  // B*C*N
    float* out           = (float*)d_out;          // B*(3+C)*S*K

    transpose_xyz_kernel<<<(B * N + 255) / 256, 256>>>(xyz);

    dim3 tg(N / 32, C / 32, B);                    // (512, 2, 4)
    transpose_feat_kernel<<<tg, dim3(32, 8)>>>(feat);

    const int grid1 = (B * S + WARPS_PER_BLOCK - 1) / WARPS_PER_BLOCK;
    ball_query_kernel<<<grid1, THREADS>>>(xyz, new_xyz, out);

    group_feat_kernel<<<B * S, 128>>>(out);
}

// round 14
// speedup vs baseline: 1.1618x; 1.1618x over previous
#include <cuda_runtime.h>
#include <cuda_bf16.h>

// QueryAndGroup, four-kernel version (3rd submission of the R11 Q=2 design;
// R12/R13 were broker-level container failures with no measurement).
//   t1: xyz (B,N,3) -> SoA xs/ys/zs
//   t2: feat (B,C,N) -> feat_T (B,N,C)            (for coalesced gathers)
//   k1: ball query, warp handles TWO queries: point loads + p2 shared across
//       both (k1 is load-wavefront bound; this cuts per-query loads ~35%).
//   k2: block-per-query grouping: coalesced 256B gathers via feat_T, smem
//       transpose, coalesced float4 channel-major stores.
// Shapes: B=4, N=16384, S=4096, C=64, K=64, radius=0.2. Out: (B, 67, S, K) f32.

namespace {
constexpr int B = 4;
constexpr int N = 16384;
constexpr int S = 4096;
constexpr int C = 64;
constexpr int K = 64;
constexpr float R2 = 0.04f;
constexpr int WARPS_PER_BLOCK = 8;
constexpr int THREADS = WARPS_PER_BLOCK * 32;
}

// Static scratch (no allocations allowed).
__device__ __align__(256) float g_featT[(size_t)B * N * C];   // 16.8 MB
__device__ __align__(16)  float g_xs[B * N];
__device__ __align__(16)  float g_ys[B * N];
__device__ __align__(16)  float g_zs[B * N];
__device__ int g_idx[B * S * K];                              // 4 MB

// p2/q2 recipe (verified rel_err == 0.0 in R7): (x^2 + z^2) + y^2, rounded muls.
__device__ __forceinline__ float sq_norm_exact(float x, float y, float z)
{
    return __fadd_rn(__fadd_rn(__fmul_rn(x, x), __fmul_rn(z, z)),
                     __fmul_rn(y, y));
}

// d2 from shared p2. qpd: ascending FMA chain (verified).
// fsub(fadd(q2,p2), fmul(2,qpd)) == fma(-2, qpd, fadd(q2,p2)) bit-identically
// (2*qpd is exact, single rounding either way).
__device__ __forceinline__ float d2_from_p2(float qx, float qy, float qz, float q2,
                                            float px, float py, float pz, float p2)
{
    const float qpd = __fmaf_rn(qz, pz, __fmaf_rn(qy, py, __fmul_rn(qx, px)));
    return __fmaf_rn(-2.0f, qpd, __fadd_rn(q2, p2));
}

// ---------------------------------------------------------------------------
// t1: xyz (B,N,3) -> SoA
// ---------------------------------------------------------------------------
__global__ void transpose_xyz_kernel(const float* __restrict__ xyz)
{
    const int i = blockIdx.x * blockDim.x + threadIdx.x;   // b*N + n
    if (i >= B * N) return;
    const float* p = xyz + (size_t)i * 3;
    g_xs[i] = p[0];
    g_ys[i] = p[1];
    g_zs[i] = p[2];
}

// ---------------------------------------------------------------------------
// t2: feat (B,C,N) -> feat_T (B,N,C), tiled smem transpose
// ---------------------------------------------------------------------------
__global__ void transpose_feat_kernel(const float* __restrict__ feat)
{
    __shared__ float tile[32][33];
    const int b  = blockIdx.z;
    const int n0 = blockIdx.x * 32;
    const int c0 = blockIdx.y * 32;
    const int tx = threadIdx.x;      // 0..31
    const int ty = threadIdx.y;      // 0..7

    const float* fb = feat + (size_t)b * C * N;
#pragma unroll
    for (int i = 0; i < 32; i += 8)
        tile[ty + i][tx] = fb[(size_t)(c0 + ty + i) * N + n0 + tx];
    __syncthreads();

    float* fo = g_featT + (size_t)b * N * C;
#pragma unroll
    for (int i = 0; i < 32; i += 8)
        fo[(size_t)(n0 + ty + i) * C + c0 + tx] = tile[tx][ty + i];
}

// ---------------------------------------------------------------------------
// k1: ball query, TWO queries per warp. 128 points per iteration (4/lane,
// lane-major: ascending order = (lane, j) lexicographic — verified layout).
// Point loads and p2 shared across both queries; each query's d2/ballot/
// select half is skipped (warp-uniform) once its K slots fill.
// ---------------------------------------------------------------------------
__global__ __launch_bounds__(THREADS)
void ball_query_kernel(const float* __restrict__ xyz,      // (B, N, 3)
                       const float* __restrict__ new_xyz,  // (B, S, 3)
                       float* __restrict__ out)            // (B, 3+C, S, K)
{
    __shared__ int s_idx[WARPS_PER_BLOCK][2][K];

    const int warp = threadIdx.x >> 5;
    const int lane = threadIdx.x & 31;
    const int wglob = blockIdx.x * WARPS_PER_BLOCK + warp;
    const int qA = wglob * 2;                 // even query
    if (qA >= B * S) return;
    const int b  = qA / S;                    // qA even, S even -> same b for both
    const int sA = qA - b * S;
    const int sB = sA + 1;

    const float* qpA = new_xyz + ((size_t)b * S + sA) * 3;
    const float* qpB = new_xyz + ((size_t)b * S + sB) * 3;
    const float qxA = qpA[0], qyA = qpA[1], qzA = qpA[2];
    const float qxB = qpB[0], qyB = qpB[1], qzB = qpB[2];
    const float q2A = sq_norm_exact(qxA, qyA, qzA);
    const float q2B = sq_norm_exact(qxB, qyB, qzB);

    const float4* xs4 = (const float4*)(g_xs + b * N);
    const float4* ys4 = (const float4*)(g_ys + b * N);
    const float4* zs4 = (const float4*)(g_zs + b * N);

    int countA = 0, countB = 0;
    const unsigned below = (1u << lane) - 1u;

    for (int base = 0; base < N; base += 128) {
        const int v = (base >> 2) + lane;
        const float4 X = xs4[v];
        const float4 Y = ys4[v];
        const float4 Z = zs4[v];

        // p2 computed once per point, shared by both queries (verified recipe)
        const float p0 = sq_norm_exact(X.x, Y.x, Z.x);
        const float p1 = sq_norm_exact(X.y, Y.y, Z.y);
        const float p2v = sq_norm_exact(X.z, Y.z, Z.z);
        const float p3 = sq_norm_exact(X.w, Y.w, Z.w);

        const int n0 = base + 4 * lane;

        if (countA < K) {   // warp-uniform
            const bool h0 = d2_from_p2(qxA, qyA, qzA, q2A, X.x, Y.x, Z.x, p0) < R2;
            const bool h1 = d2_from_p2(qxA, qyA, qzA, q2A, X.y, Y.y, Z.y, p1) < R2;
            const bool h2 = d2_from_p2(qxA, qyA, qzA, q2A, X.z, Y.z, Z.z, p2v) < R2;
            const bool h3 = d2_from_p2(qxA, qyA, qzA, q2A, X.w, Y.w, Z.w, p3) < R2;
            const unsigned m0 = __ballot_sync(0xffffffffu, h0);
            const unsigned m1 = __ballot_sync(0xffffffffu, h1);
            const unsigned m2 = __ballot_sync(0xffffffffu, h2);
            const unsigned m3 = __ballot_sync(0xffffffffu, h3);
            int p = countA + __popc(m0 & below) + __popc(m1 & below)
                          + __popc(m2 & below) + __popc(m3 & below);
            if (h0 && p < K) s_idx[warp][0][p] = n0;
            p += h0;
            if (h1 && p < K) s_idx[warp][0][p] = n0 + 1;
            p += h1;
            if (h2 && p < K) s_idx[warp][0][p] = n0 + 2;
            p += h2;
            if (h3 && p < K) s_idx[warp][0][p] = n0 + 3;
            countA += __popc(m0) + __popc(m1) + __popc(m2) + __popc(m3);
        }

        if (countB < K) {   // warp-uniform
            const bool h0 = d2_from_p2(qxB, qyB, qzB, q2B, X.x, Y.x, Z.x, p0) < R2;
            const bool h1 = d2_from_p2(qxB, qyB, qzB, q2B, X.y, Y.y, Z.y, p1) < R2;
            const bool h2 = d2_from_p2(qxB, qyB, qzB, q2B, X.z, Y.z, Z.z, p2v) < R2;
            const bool h3 = d2_from_p2(qxB, qyB, qzB, q2B, X.w, Y.w, Z.w, p3) < R2;
            const unsigned m0 = __ballot_sync(0xffffffffu, h0);
            const unsigned m1 = __ballot_sync(0xffffffffu, h1);
            const unsigned m2 = __ballot_sync(0xffffffffu, h2);
            const unsigned m3 = __ballot_sync(0xffffffffu, h3);
            int p = countB + __popc(m0 & below) + __popc(m1 & below)
                          + __popc(m2 & below) + __popc(m3 & below);
            if (h0 && p < K) s_idx[warp][1][p] = n0;
            p += h0;
            if (h1 && p < K) s_idx[warp][1][p] = n0 + 1;
            p += h1;
            if (h2 && p < K) s_idx[warp][1][p] = n0 + 2;
            p += h2;
            if (h3 && p < K) s_idx[warp][1][p] = n0 + 3;
            countB += __popc(m0) + __popc(m1) + __popc(m2) + __popc(m3);
        }

        if (countA >= K && countB >= K) break;
    }
    __syncwarp();

    const int k0 = 2 * lane;
    const float* xb = xyz + (size_t)b * N * 3;
    const size_t chan_stride = (size_t)S * K;

#pragma unroll
    for (int half = 0; half < 2; ++half) {
        const int count = half ? countB : countA;
        const int s     = half ? sB : sA;
        const float qx  = half ? qxB : qxA;
        const float qy  = half ? qyB : qyA;
        const float qz  = half ? qzB : qzA;

        const int cnt = (count < K) ? count : K;
        const int fill = (cnt > 0) ? s_idx[warp][half][0] : 0;
        if (k0 >= cnt)     s_idx[warp][half][k0]     = fill;
        if (k0 + 1 >= cnt) s_idx[warp][half][k0 + 1] = fill;
        __syncwarp();

        const int i0 = s_idx[warp][half][k0];
        const int i1 = s_idx[warp][half][k0 + 1];

        *reinterpret_cast<int2*>(g_idx + ((size_t)b * S + s) * K + k0) =
            make_int2(i0, i1);

        float* ob = out + (size_t)b * (3 + C) * chan_stride + (size_t)s * K + k0;
        const float x0 = xb[3 * i0 + 0], y0 = xb[3 * i0 + 1], z0 = xb[3 * i0 + 2];
        const float x1 = xb[3 * i1 + 0], y1 = xb[3 * i1 + 1], z1 = xb[3 * i1 + 2];
        *reinterpret_cast<float2*>(ob + 0 * chan_stride) =
            make_float2(__fsub_rn(x0, qx), __fsub_rn(x1, qx));
        *reinterpret_cast<float2*>(ob + 1 * chan_stride) =
            make_float2(__fsub_rn(y0, qy), __fsub_rn(y1, qy));
        *reinterpret_cast<float2*>(ob + 2 * chan_stride) =
            make_float2(__fsub_rn(z0, qz), __fsub_rn(z1, qz));
    }
}

// ---------------------------------------------------------------------------
// k2: grouping. Block = one query (128 threads). Gather 64 indices x 256B
// (coalesced: 16 lanes per index, LDG.128), stage transposed in smem
// [k][c] with +1 padding, then write channel-major float4 coalesced.
// ---------------------------------------------------------------------------
__global__ __launch_bounds__(128)
void group_feat_kernel(float* __restrict__ out)
{
    __shared__ int   sidx[K];
    __shared__ float sdata[K][C + 1];   // 64 x 65 floats, pad limits conflicts

    const int q = blockIdx.x;
    const int b = q / S;
    const int s = q - b * S;
    const int t = threadIdx.x;

    if (t < 16)
        *reinterpret_cast<int4*>(sidx + t * 4) =
            *reinterpret_cast<const int4*>(g_idx + (size_t)q * K + t * 4);
    __syncthreads();

    const float* ft = g_featT + (size_t)b * N * C;

    // Gather phase: 1024 float4 slots (64 idx x 16 parts), 8 per thread.
#pragma unroll
    for (int jj = 0; jj < 8; ++jj) {
        const int slot = jj * 128 + t;
        const int k    = slot >> 4;
        const int part = slot & 15;
        const int idx  = sidx[k];
        const float4 v = *reinterpret_cast<const float4*>(ft + (size_t)idx * C + part * 4);
        float* d = &sdata[k][part * 4];
        d[0] = v.x; d[1] = v.y; d[2] = v.z; d[3] = v.w;
    }
    __syncthreads();

    // Write phase: out[b][3+c][s][k], 1024 float4 slots (64 c x 16 k-parts).
    float* ob = out + ((size_t)b * (3 + C) + 3) * ((size_t)S * K) + (size_t)s * K;
#pragma unroll
    for (int jj = 0; jj < 8; ++jj) {
        const int slot = jj * 128 + t;
        const int c    = slot >> 4;
        const int kp   = (slot & 15) * 4;
        const float4 v = make_float4(sdata[kp + 0][c], sdata[kp + 1][c],
                                     sdata[kp + 2][c], sdata[kp + 3][c]);
        *reinterpret_cast<float4*>(ob + (size_t)c * (S * K) + kp) = v;
    }
}

extern "C" void kernel_launch(void* const* d_in, const int* in_sizes, int n_in,
                              void* d_out, int out_size)
{
    const float* xyz     = (const float*)d_in[0];  // B*N*3
    const float* new_xyz = (const float*)d_in[1];  // B*S*3
    const float* feat    = (const float*)d_in[2];  // B*C*N
    float* out           = (float*)d_out;          // B*(3+C)*S*K

    transpose_xyz_kernel<<<(B * N + 255) / 256, 256>>>(xyz);

    dim3 tg(N / 32, C / 32, B);                    // (512, 2, 4)
    transpose_feat_kernel<<<tg, dim3(32, 8)>>>(feat);

    const int warp_pairs = B * S / 2;              // 8192 warps, 2 queries each
    const int grid1 = (warp_pairs + WARPS_PER_BLOCK - 1) / WARPS_PER_BLOCK;
    ball_query_kernel<<<grid1, THREADS>>>(xyz, new_xyz, out);

    group_feat_kernel<<<B * S, 128>>>(out);
}